// round 12
// baseline (speedup 1.0000x reference)
#include <cuda_runtime.h>

// Problem constants
#define BB 2
#define NN 512
#define FF 128
#define HH 256          // 2F
#define NEG_SLOPE 0.04f
#define MASK_VAL  (-9e15f)

#define BN (BB*NN)      // 1024 rows total

// Scratch, both transposed: PBT[h][bn] = p + b1,  QT[h][bn] = q
__device__ float g_PBT[HH * BN];
__device__ float g_QT[HH * BN];

// ---------------------------------------------------------------------------
// Kernel 1: fused p/q projection. 128 blocks x 512 threads, 8 rows/block.
// Thread: h = tid&255, row-half rg = tid>>8 (rows rg*4 .. rg*4+3).
// ---------------------------------------------------------------------------
__global__ __launch_bounds__(512) void pq_kernel(
    const float* __restrict__ x,
    const float* __restrict__ w1,
    const float* __restrict__ b1)
{
    __shared__ float xs[8 * FF];          // 8 rows x 128
    const int tid = threadIdx.x;
    const int bn0 = blockIdx.x * 8;

    if (tid < 256)                         // 1024 floats = 256 float4
        ((float4*)xs)[tid] = ((const float4*)(x + (size_t)bn0 * FF))[tid];
    __syncthreads();

    const int h  = tid & 255;
    const int rb = (tid >> 8) * 4;         // row base 0 or 4
    const float* __restrict__ wrow = w1 + (size_t)h * (2 * FF);
    const float* __restrict__ xr   = xs + rb * FF;

    float accP[4] = {0.f, 0.f, 0.f, 0.f};
    float accQ[4] = {0.f, 0.f, 0.f, 0.f};

#pragma unroll 4
    for (int f = 0; f < FF; f += 4) {
        const float4 wp = *(const float4*)(wrow + f);        // L1-resident
        const float4 wq = *(const float4*)(wrow + FF + f);
#pragma unroll
        for (int r = 0; r < 4; ++r) {
            const float x0 = xr[r * FF + f + 0];             // broadcast
            const float x1 = xr[r * FF + f + 1];
            const float x2 = xr[r * FF + f + 2];
            const float x3 = xr[r * FF + f + 3];
            accP[r] = fmaf(x0, wp.x, accP[r]);
            accP[r] = fmaf(x1, wp.y, accP[r]);
            accP[r] = fmaf(x2, wp.z, accP[r]);
            accP[r] = fmaf(x3, wp.w, accP[r]);
            accQ[r] = fmaf(x0, wq.x, accQ[r]);
            accQ[r] = fmaf(x1, wq.y, accQ[r]);
            accQ[r] = fmaf(x2, wq.z, accQ[r]);
            accQ[r] = fmaf(x3, wq.w, accQ[r]);
        }
    }

    const float b1h = b1[h];
    float4 pa = make_float4(accP[0] + b1h, accP[1] + b1h,
                            accP[2] + b1h, accP[3] + b1h);
    float4 qa = make_float4(accQ[0], accQ[1], accQ[2], accQ[3]);
    *(float4*)(g_PBT + (size_t)h * BN + bn0 + rb) = pa;
    *(float4*)(g_QT  + (size_t)h * BN + bn0 + rb) = qa;
}

// ---------------------------------------------------------------------------
// Kernel 2: e-scores + leaky + mask + softmax + att@x, fused.
// 128 blocks (b x 64 i-tiles of 8 rows), 512 threads.
// Thread e-tile: 4 rows (r0 = (tid>>8)*4) x 2 j (j0 = 2*(tid&255)).
// Q tile double-buffered (1 sync/chunk); all chunk operands hoisted to regs.
// ---------------------------------------------------------------------------
__global__ __launch_bounds__(512) void attn_kernel(
    const float* __restrict__ x,
    const float* __restrict__ w2,
    const float* __restrict__ b2,
    const int*   __restrict__ adj,
    float* __restrict__ out,
    int write_att)
{
    __shared__ float q_sm[2 * 8 * NN];   // 32 KB double buffer (later: att + spare)
    __shared__ float a_sm[HH * 8];       // 8 KB, a_sm[h*8+r]   (later: AV partials)
    __shared__ float w2_sm[HH];          // 1 KB
    __shared__ float redm[8][8];
    __shared__ float reds[8][8];

    const int tid = threadIdx.x;           // 0..511
    const int jt  = tid & 255;
    const int j0  = 2 * jt;                // j0, j0+1
    const int rg  = tid >> 8;              // 0 / 1
    const int r0  = rg * 4;                // rows r0..r0+3
    const int b   = blockIdx.x >> 6;
    const int it0 = (blockIdx.x & 63) << 3;
    const int base = b * NN + it0;

    // ---- stage a (transposed PB tile): a_sm[h*8 + r], 2048 floats --------
    {
        const int h    = tid >> 1;
        const int half = (tid & 1) * 4;
        *(float4*)(a_sm + h * 8 + half) =
            *(const float4*)(g_PBT + (size_t)h * BN + base + half);
    }
    if (tid < HH) w2_sm[tid] = w2[tid];

    // ---- q producer state (copies 8h x 512j chunk = 1024 float4) ---------
    const float* __restrict__ qtb = g_QT + (size_t)b * NN;
    const int jf  = tid & 127;
    const int hcA = tid >> 7;              // 0..3
    const float4* src0 = (const float4*)(qtb + (size_t)hcA * BN) + jf;
    const float4* src1 = (const float4*)(qtb + (size_t)(hcA + 4) * BN) + jf;

    float4 pre0 = *src0;
    float4 pre1 = *src1;
    ((float4*)q_sm)[tid]       = pre0;     // chunk 0 -> buffer 0
    ((float4*)q_sm)[tid + 512] = pre1;
    __syncthreads();

    float e[4][2];
#pragma unroll
    for (int r = 0; r < 4; ++r) { e[r][0] = 0.f; e[r][1] = 0.f; }

    const float* asrc = a_sm + r0;         // + h*8

    for (int c = 0; c < 32; ++c) {
        const float* cur = q_sm + (c & 1) * (8 * NN);
        float*       nxt = q_sm + ((c + 1) & 1) * (8 * NN);

        if (c + 1 < 32) {                  // fire next chunk's global loads
            src0 += 2 * BN;                // 8 rows of BN floats, in float4s
            src1 += 2 * BN;
            pre0 = *src0;
            pre1 = *src1;
        }

        // hoist ALL chunk operands into registers (latency buried below)
        float2 qv[8];
        float4 av[8];
        float  wv[8];
#pragma unroll
        for (int hc = 0; hc < 8; ++hc)
            qv[hc] = *(const float2*)(cur + hc * NN + j0);
#pragma unroll
        for (int hc = 0; hc < 8; ++hc)
            av[hc] = *(const float4*)(asrc + (c * 8 + hc) * 8);
        *(float4*)(wv)     = *(const float4*)(w2_sm + c * 8);
        *(float4*)(wv + 4) = *(const float4*)(w2_sm + c * 8 + 4);

#pragma unroll
        for (int hc = 0; hc < 8; ++hc) {
            const float qx = qv[hc].x, qy = qv[hc].y, w = wv[hc];
            e[0][0] = fmaf(fmaxf(av[hc].x + qx, 0.f), w, e[0][0]);
            e[0][1] = fmaf(fmaxf(av[hc].x + qy, 0.f), w, e[0][1]);
            e[1][0] = fmaf(fmaxf(av[hc].y + qx, 0.f), w, e[1][0]);
            e[1][1] = fmaf(fmaxf(av[hc].y + qy, 0.f), w, e[1][1]);
            e[2][0] = fmaf(fmaxf(av[hc].z + qx, 0.f), w, e[2][0]);
            e[2][1] = fmaf(fmaxf(av[hc].z + qy, 0.f), w, e[2][1]);
            e[3][0] = fmaf(fmaxf(av[hc].w + qx, 0.f), w, e[3][0]);
            e[3][1] = fmaf(fmaxf(av[hc].w + qy, 0.f), w, e[3][1]);
        }

        if (c + 1 < 32) {                  // stage next chunk (other buffer)
            ((float4*)nxt)[tid]       = pre0;
            ((float4*)nxt)[tid + 512] = pre1;
        }
        __syncthreads();                   // nxt ready; cur free for c+2
    }

    // ---- leaky relu + adjacency mask (int2, coalesced) -------------------
    const float b2v = b2[0];
    const int* __restrict__ adjb = adj + (size_t)(base + r0) * NN;
#pragma unroll
    for (int r = 0; r < 4; ++r) {
        const int2 m = *(const int2*)(adjb + (size_t)r * NN + j0);
        float v0 = e[r][0] + b2v;
        float v1 = e[r][1] + b2v;
        v0 = (v0 > 0.f) ? v0 : NEG_SLOPE * v0;
        v1 = (v1 > 0.f) ? v1 : NEG_SLOPE * v1;
        e[r][0] = (m.x > 0) ? v0 : MASK_VAL;
        e[r][1] = (m.y > 0) ? v1 : MASK_VAL;
    }

    // ---- softmax over j: shfl within warp, 8-warp combine in smem --------
    const int wig = (tid >> 5) & 7;        // warp index within row group
    float mr[4];
#pragma unroll
    for (int r = 0; r < 4; ++r) mr[r] = fmaxf(e[r][0], e[r][1]);
#pragma unroll
    for (int off = 16; off > 0; off >>= 1) {
#pragma unroll
        for (int r = 0; r < 4; ++r)
            mr[r] = fmaxf(mr[r], __shfl_xor_sync(0xffffffffu, mr[r], off));
    }
    if ((tid & 31) == 0) {
#pragma unroll
        for (int r = 0; r < 4; ++r) redm[r0 + r][wig] = mr[r];
    }
    __syncthreads();
    float mx[4];
#pragma unroll
    for (int r = 0; r < 4; ++r) {
        float m = redm[r0 + r][0];
#pragma unroll
        for (int k = 1; k < 8; ++k) m = fmaxf(m, redm[r0 + r][k]);
        mx[r] = m;
    }

    float sr[4];
#pragma unroll
    for (int r = 0; r < 4; ++r) {
        e[r][0] = __expf(e[r][0] - mx[r]);
        e[r][1] = __expf(e[r][1] - mx[r]);
        sr[r] = e[r][0] + e[r][1];
    }
#pragma unroll
    for (int off = 16; off > 0; off >>= 1) {
#pragma unroll
        for (int r = 0; r < 4; ++r)
            sr[r] += __shfl_xor_sync(0xffffffffu, sr[r], off);
    }
    if ((tid & 31) == 0) {
#pragma unroll
        for (int r = 0; r < 4; ++r) reds[r0 + r][wig] = sr[r];
    }
    __syncthreads();

    // ---- attention tile into q_sm buffer 0 -------------------------------
    float* att = q_sm;
#pragma unroll
    for (int r = 0; r < 4; ++r) {
        float s = reds[r0 + r][0];
#pragma unroll
        for (int k = 1; k < 8; ++k) s += reds[r0 + r][k];
        const float inv = 1.0f / s;
        *(float2*)(att + (r0 + r) * NN + j0) =
            make_float2(e[r][0] * inv, e[r][1] * inv);
    }
    __syncthreads();

    // attention[0,0,:] output (block 0 holds b=0, i=0 at row 0)
    if (write_att && blockIdx.x == 0)
        out[BB * NN * FF + tid] = att[tid];     // row 0 = att[0..511]

    // ---- next_h[b, it0+rw, f] = sum_j att[rw][j] * x[b, j, f] -------------
    // thread = (f-quad fq, row rw, j-half); halves combined via a_sm.
    const int fq   = tid & 31;             // f = 4*fq..4*fq+3
    const int rw   = (tid >> 5) & 7;       // row 0..7
    const int half = tid >> 8;             // j in [0,256) / [256,512)
    const float* __restrict__ arow = att + rw * NN + half * 256;
    const float* __restrict__ xrow = x + (size_t)b * NN * FF
                                       + (size_t)half * 256 * FF + 4 * fq;

    float4 acc = make_float4(0.f, 0.f, 0.f, 0.f);
#pragma unroll 2
    for (int jj = 0; jj < 256; jj += 4) {
        const float4 a4 = *(const float4*)(arow + jj);            // broadcast
        const float4 x0 = *(const float4*)(xrow + (size_t)(jj + 0) * FF);
        const float4 x1 = *(const float4*)(xrow + (size_t)(jj + 1) * FF);
        const float4 x2 = *(const float4*)(xrow + (size_t)(jj + 2) * FF);
        const float4 x3 = *(const float4*)(xrow + (size_t)(jj + 3) * FF);
        acc.x = fmaf(a4.x, x0.x, acc.x);
        acc.y = fmaf(a4.x, x0.y, acc.y);
        acc.z = fmaf(a4.x, x0.z, acc.z);
        acc.w = fmaf(a4.x, x0.w, acc.w);
        acc.x = fmaf(a4.y, x1.x, acc.x);
        acc.y = fmaf(a4.y, x1.y, acc.y);
        acc.z = fmaf(a4.y, x1.z, acc.z);
        acc.w = fmaf(a4.y, x1.w, acc.w);
        acc.x = fmaf(a4.z, x2.x, acc.x);
        acc.y = fmaf(a4.z, x2.y, acc.y);
        acc.z = fmaf(a4.z, x2.z, acc.z);
        acc.w = fmaf(a4.z, x2.w, acc.w);
        acc.x = fmaf(a4.w, x3.x, acc.x);
        acc.y = fmaf(a4.w, x3.y, acc.y);
        acc.z = fmaf(a4.w, x3.z, acc.z);
        acc.w = fmaf(a4.w, x3.w, acc.w);
    }

    // combine halves through a_sm (its previous contents are dead now)
    if (half == 1)
        *(float4*)(a_sm + rw * FF + 4 * fq) = acc;
    __syncthreads();
    if (half == 0) {
        const float4 p = *(const float4*)(a_sm + rw * FF + 4 * fq);
        acc.x += p.x; acc.y += p.y; acc.z += p.z; acc.w += p.w;
        *(float4*)(out + (size_t)(base + rw) * FF + 4 * fq) = acc;
    }
}

// ---------------------------------------------------------------------------
// Launch. Input order per setup_inputs: x, w1, b1, w2, b2, adj
// Output: next_h (2*512*128 floats) then attention[0,0,:] (512 floats)
// ---------------------------------------------------------------------------
extern "C" void kernel_launch(void* const* d_in, const int* in_sizes, int n_in,
                              void* d_out, int out_size)
{
    const float* x   = (const float*)d_in[0];
    const float* w1  = (const float*)d_in[1];
    const float* b1  = (const float*)d_in[2];
    const float* w2  = (const float*)d_in[3];
    const float* b2  = (const float*)d_in[4];
    const int*   adj = (const int*)  d_in[5];
    float* out = (float*)d_out;

    const int write_att = (out_size >= BB * NN * FF + NN) ? 1 : 0;

    pq_kernel<<<BN / 8, 512>>>(x, w1, b1);
    attn_kernel<<<BB * (NN / 8), 512>>>(x, w2, b2, adj, out, write_att);
}